// round 13
// baseline (speedup 1.0000x reference)
#include <cuda_runtime.h>

// RNN-T transducer loss. B=16, T=200, U=101, A=512, blank=0.
// LOG2-domain split lattice (exact), barrier-free shfl schedule, 8x unroll,
// float2-packed operand tables, NEG-init seeding.
// r13: inner step rewritten in explicit phases across the 4 column-chains
// (loads -> shfls -> adds -> minmax -> ex2 x4 -> lg2 x4 -> commit) so ptxas
// interleaves the four independent lae chains instead of serializing them.
// Identical fp ops/order per value vs r12 => bit-identical result.

#define BQ 16
#define TM 200
#define UM 101
#define AA 512
#define UP 104
#define HR 100           // max rows per half (ts<=100, nbk<=100)
#define NEG (-1.0e30f)
#define LOG2E 1.4426950408889634f
#define LN2   0.6931471805599453f
#define FULL  0xffffffffu

// Packed log2-domain tables (zero-initialized .bss; unwritten slots stay 0).
// g_pf[b][t][u] = (blk[t-1][u], emS[t][u])  for t in [0,ts)   (fwd half)
// g_pw[b][r][u] = (blk[ts+r][u], emit[ts+r][u]) for r in [0,nbk) (bwd half)
__device__ __align__(16) float2 g_pf[BQ][HR][UP];
__device__ __align__(16) float2 g_pw[BQ][HR][UP];
__device__ float g_jblk[BQ][UP];   // blk[ts-1][u]
__device__ float g_logp[BQ];
__device__ int   g_cnt = 0;

__device__ __forceinline__ float ex2(float x) { float y; asm("ex2.approx.f32 %0, %1;" : "=f"(y) : "f"(x)); return y; }
__device__ __forceinline__ float lg2(float x) { float y; asm("lg2.approx.f32 %0, %1;" : "=f"(y) : "f"(x)); return y; }

__global__ void tl_gather_kernel(const float* __restrict__ lp,
                                 const int*   __restrict__ labels,
                                 const int*   __restrict__ Tarr)
{
    const int total  = BQ * TM * UM;
    const int stride = gridDim.x * blockDim.x;
    int i0 = blockIdx.x * blockDim.x + threadIdx.x;
    #pragma unroll
    for (int kk = 0; kk < 4; ++kk) {
        int i = i0 + kk * stride;
        if (i < total) {
            int u  = i % UM;
            int bt = i / UM;
            int t  = bt % TM;
            int b  = bt / TM;
            int lab = (u < UM - 1) ? __ldg(labels + b * (UM - 1) + u) : 0;
            size_t base = (size_t)i * AA;
            float bv = __ldg(lp + base) * LOG2E;                   // blk[t][u]
            float ev = lab ? __ldg(lp + base + lab) * LOG2E : bv;  // emit[t][u]
            int Tb = __ldg(Tarr + b);
            int ts = (Tb + 1) >> 1;
            if (t < ts) {
                if (t + 1 < ts) g_pf[b][t + 1][u].x = bv;   // blk[t][u] -> row t+1
                g_pf[b][t][u + 1].y = ev;                   // emS[t][u+1] = emit[t][u]
                if (t == ts - 1) g_jblk[b][u] = bv;
            } else if (t < Tb) {
                g_pw[b][t - ts][u] = make_float2(bv, ev);
            }
        }
    }
}

__global__ __launch_bounds__(256, 1)
void tl_lattice_kernel(const int* __restrict__ Tarr,
                       const int* __restrict__ Uarr,
                       float* __restrict__ out)
{
    extern __shared__ float sm[];
    float2* s_pf = (float2*)sm;              // [HR][UP] fwd pairs
    float2* s_pw = s_pf + HR * UP;           // [HR][UP] bwd pairs
    __shared__ float s_ja[UP], s_jb[UP];

    const int b    = blockIdx.x;
    const int tid  = threadIdx.x;
    const int lane = tid & 31;
    const int wid  = tid >> 5;

    {   // stage packed tables (coalesced float4, 8 warps)
        const float4* gf = (const float4*)&g_pf[b][0][0];
        const float4* gw = (const float4*)&g_pw[b][0][0];
        float4* sf = (float4*)s_pf;
        float4* sw = (float4*)s_pw;
        const int n4 = HR * UP / 2;          // 5200 float4 per half
        for (int k = tid; k < n4; k += 256) { sf[k] = gf[k]; sw[k] = gw[k]; }
    }
    if (tid < UP) { s_ja[tid] = NEG; s_jb[tid] = 0.0f; }

    const int Tb  = __ldg(Tarr + b);
    const int Ub  = __ldg(Uarr + b);
    const int ts  = (Tb + 1) >> 1;           // fwd rows [0,ts)
    const int nbk = Tb - ts;                 // bwd rows [ts,Tb)
    __syncthreads();

    const int src = (lane + 31) & 31;        // rotate-up source lane

    if (wid == 0) {
        // ---------------- forward: alpha over rows [0, ts) ----------------
        const int R = ts;
        const int nsteps = R + Ub;
        int uu[4], uc[4];
        float jb4[4];
        #pragma unroll
        for (int j = 0; j < 4; ++j) {
            uu[j] = lane + 32 * j;
            uc[j] = min(uu[j], UP - 1);
            jb4[j] = __ldg(&g_jblk[b][uc[j]]);
        }
        float h[4] = {(lane == 0) ? 0.0f : NEG, NEG, NEG, NEG};

        for (int s0 = 1; s0 < nsteps; s0 += 8) {
            #pragma unroll
            for (int ds = 0; ds < 8; ++ds) {
                const int s = s0 + ds;
                // phase 0: operand loads (independent of h)
                int t[4]; float2 pv[4];
                #pragma unroll
                for (int j = 0; j < 4; ++j) {
                    t[j] = s - uu[j];
                    const unsigned tc = min((unsigned)t[j], (unsigned)(R - 1));
                    pv[j] = s_pf[tc * UP + uc[j]];
                }
                // phase 1: all shfls
                float r[4];
                #pragma unroll
                for (int j = 0; j < 4; ++j) r[j] = __shfl_sync(FULL, h[j], src);
                // phase 2: ver/hor for all chains
                float ver[4], hor[4];
                #pragma unroll
                for (int j = 0; j < 4; ++j) {
                    const float hin = lane ? r[j] : (j ? r[j - 1] : NEG);
                    ver[j] = h[j] + pv[j].x;
                    hor[j] = hin  + pv[j].y;
                }
                // phase 3: max / delta
                float m[4], d[4];
                #pragma unroll
                for (int j = 0; j < 4; ++j) {
                    m[j] = fmaxf(ver[j], hor[j]);
                    d[j] = fminf(ver[j], hor[j]) - m[j];
                }
                // phase 4: all ex2
                float e[4];
                #pragma unroll
                for (int j = 0; j < 4; ++j) e[j] = ex2(d[j]);
                // phase 5: all lg2
                float l[4];
                #pragma unroll
                for (int j = 0; j < 4; ++j) l[j] = lg2(1.0f + e[j]);
                // phase 6: commit
                #pragma unroll
                for (int j = 0; j < 4; ++j) {
                    const float val = m[j] + l[j];
                    h[j] = ((unsigned)t[j] < (unsigned)R) ? val : h[j];
                }
            }
        }
        #pragma unroll
        for (int j = 0; j < 4; ++j)
            if (uu[j] <= Ub) s_ja[uu[j]] = h[j] + jb4[j];
    } else if (wid == 1) {
        // ------------- backward: beta rows [ts,Tb), mirrored coords -------
        const int R = nbk;
        const int nsteps = R + Ub;
        const float seedB = s_pw[(R - 1) * UP + Ub].x;     // blk[Tb-1][Ub]
        int vv[4], ucb[4];
        #pragma unroll
        for (int j = 0; j < 4; ++j) {
            vv[j]  = lane + 32 * j;
            ucb[j] = min(max(Ub - vv[j], 0), UP - 1);
        }
        float h[4] = {(lane == 0) ? seedB : NEG, NEG, NEG, NEG};

        for (int s0 = 1; s0 < nsteps; s0 += 8) {
            #pragma unroll
            for (int ds = 0; ds < 8; ++ds) {
                const int s = s0 + ds;
                int tp[4]; float2 pv[4];
                #pragma unroll
                for (int j = 0; j < 4; ++j) {
                    tp[j] = s - vv[j];
                    const unsigned tpc = min((unsigned)tp[j], (unsigned)(R - 1));
                    const unsigned rb  = (unsigned)(R - 1) - tpc;
                    pv[j] = s_pw[rb * UP + ucb[j]];
                }
                float r[4];
                #pragma unroll
                for (int j = 0; j < 4; ++j) r[j] = __shfl_sync(FULL, h[j], src);
                float ver[4], hor[4];
                #pragma unroll
                for (int j = 0; j < 4; ++j) {
                    const float hin = lane ? r[j] : (j ? r[j - 1] : NEG);
                    ver[j] = h[j] + pv[j].x;
                    hor[j] = hin  + pv[j].y;
                }
                float m[4], d[4];
                #pragma unroll
                for (int j = 0; j < 4; ++j) {
                    m[j] = fmaxf(ver[j], hor[j]);
                    d[j] = fminf(ver[j], hor[j]) - m[j];
                }
                float e[4];
                #pragma unroll
                for (int j = 0; j < 4; ++j) e[j] = ex2(d[j]);
                float l[4];
                #pragma unroll
                for (int j = 0; j < 4; ++j) l[j] = lg2(1.0f + e[j]);
                #pragma unroll
                for (int j = 0; j < 4; ++j) {
                    const float val = m[j] + l[j];
                    h[j] = ((unsigned)tp[j] < (unsigned)R) ? val : h[j];
                }
            }
        }
        #pragma unroll
        for (int j = 0; j < 4; ++j) {
            const int u = Ub - vv[j];
            if (u >= 0) s_jb[u] = h[j];
        }
    }
    __syncthreads();

    // log_p = LN2 * LSE2_u(ja[u] + jb[u])   (warp 0)
    if (tid < 32) {
        float x0 = (tid      < UP) ? s_ja[tid]      + s_jb[tid]      : NEG;
        float x1 = (tid + 32 < UP) ? s_ja[tid + 32] + s_jb[tid + 32] : NEG;
        float x2 = (tid + 64 < UP) ? s_ja[tid + 64] + s_jb[tid + 64] : NEG;
        float x3 = (tid + 96 < UP) ? s_ja[tid + 96] + s_jb[tid + 96] : NEG;
        float m = fmaxf(fmaxf(x0, x1), fmaxf(x2, x3));
        #pragma unroll
        for (int o = 16; o > 0; o >>= 1)
            m = fmaxf(m, __shfl_xor_sync(FULL, m, o));
        float sum2 = ex2(x0 - m) + ex2(x1 - m) + ex2(x2 - m) + ex2(x3 - m);
        #pragma unroll
        for (int o = 16; o > 0; o >>= 1)
            sum2 += __shfl_xor_sync(FULL, sum2, o);
        if (tid == 0) g_logp[b] = (m + lg2(sum2)) * LN2;
    }
    __syncthreads();

    // fixed-order mean reduction in the last-arriving CTA (deterministic)
    if (tid == 0) {
        __threadfence();
        int old = atomicAdd(&g_cnt, 1);
        if (old == BQ - 1) {
            __threadfence();
            float ssum = 0.0f;
            #pragma unroll
            for (int i = 0; i < BQ; ++i) ssum += g_logp[i];
            out[0] = -ssum / (float)BQ;
            g_cnt = 0;                       // reset for next graph replay
        }
    }
}

extern "C" void kernel_launch(void* const* d_in, const int* in_sizes, int n_in,
                              void* d_out, int out_size)
{
    const float* lp     = (const float*)d_in[0];
    const int*   labels = (const int*)  d_in[1];
    const int*   Tarr   = (const int*)  d_in[2];
    const int*   Uarr   = (const int*)  d_in[3];
    float* out = (float*)d_out;

    const int smem_bytes = 2 * HR * UP * (int)sizeof(float2);  // 166,400
    cudaFuncSetAttribute(tl_lattice_kernel,
                         cudaFuncAttributeMaxDynamicSharedMemorySize,
                         smem_bytes);

    const int total  = BQ * TM * UM;
    const int blocks = (total + 256 * 4 - 1) / (256 * 4);      // 316
    tl_gather_kernel<<<blocks, 256>>>(lp, labels, Tarr);
    tl_lattice_kernel<<<BQ, 256, smem_bytes>>>(Tarr, Uarr, out);
}

// round 14
// speedup vs baseline: 1.0789x; 1.0789x over previous
#include <cuda_runtime.h>

// RNN-T transducer loss. B=16, T=200, U=101, A=512, blank=0.
// LOG2-domain split lattice with LAZY representation: running value kept as
// (m, f) with h = m + lg2(f), f in [1, 2^9) via exact per-block exponent
// folding. lae becomes: M = max(mv,mh); f' = f_big + f_small * ex2(-|d|)
// -- mathematically identical to lae2, but lg2 runs ONCE at the junction.
// 1 MUFU per cell (was 2), no lg2 on the chain, nothing can underflow.
// Schedule: r12's proven barrier-free shfl wavefront, 8x unroll,
// float2-packed tables; warp0 fwd rows [0,ts), warp1 bwd rows [ts,Tb).

#define BQ 16
#define TM 200
#define UM 101
#define AA 512
#define UP 104
#define HR 100           // max rows per half (ts<=100, nbk<=100)
#define NEG (-1.0e30f)
#define LOG2E 1.4426950408889634f
#define LN2   0.6931471805599453f
#define FULL  0xffffffffu

// Packed log2-domain tables (zero-initialized .bss; unwritten slots stay 0).
// g_pf[b][t][u] = (blk[t-1][u], emS[t][u])      for t in [0,ts)
// g_pw[b][r][u] = (blk[ts+r][u], emit[ts+r][u]) for r in [0,nbk)
__device__ __align__(16) float2 g_pf[BQ][HR][UP];
__device__ __align__(16) float2 g_pw[BQ][HR][UP];
__device__ float g_jblk[BQ][UP];   // blk[ts-1][u]
__device__ float g_logp[BQ];
__device__ int   g_cnt = 0;

__device__ __forceinline__ float ex2(float x) { float y; asm("ex2.approx.f32 %0, %1;" : "=f"(y) : "f"(x)); return y; }
__device__ __forceinline__ float lg2(float x) { float y; asm("lg2.approx.f32 %0, %1;" : "=f"(y) : "f"(x)); return y; }
__device__ __forceinline__ float fneg(float x) { return __int_as_float(__float_as_int(x) ^ 0x80000000); }

__global__ void tl_gather_kernel(const float* __restrict__ lp,
                                 const int*   __restrict__ labels,
                                 const int*   __restrict__ Tarr)
{
    const int total  = BQ * TM * UM;
    const int stride = gridDim.x * blockDim.x;
    int i0 = blockIdx.x * blockDim.x + threadIdx.x;
    #pragma unroll
    for (int kk = 0; kk < 4; ++kk) {
        int i = i0 + kk * stride;
        if (i < total) {
            int u  = i % UM;
            int bt = i / UM;
            int t  = bt % TM;
            int b  = bt / TM;
            int lab = (u < UM - 1) ? __ldg(labels + b * (UM - 1) + u) : 0;
            size_t base = (size_t)i * AA;
            float bv = __ldg(lp + base) * LOG2E;                   // blk[t][u]
            float ev = lab ? __ldg(lp + base + lab) * LOG2E : bv;  // emit[t][u]
            int Tb = __ldg(Tarr + b);
            int ts = (Tb + 1) >> 1;
            if (t < ts) {
                if (t + 1 < ts) g_pf[b][t + 1][u].x = bv;   // blk[t][u] -> row t+1
                g_pf[b][t][u + 1].y = ev;                   // emS[t][u+1] = emit[t][u]
                if (t == ts - 1) g_jblk[b][u] = bv;
            } else if (t < Tb) {
                g_pw[b][t - ts][u] = make_float2(bv, ev);
            }
        }
    }
}

__global__ __launch_bounds__(256, 1)
void tl_lattice_kernel(const int* __restrict__ Tarr,
                       const int* __restrict__ Uarr,
                       float* __restrict__ out)
{
    extern __shared__ float sm[];
    float2* s_pf = (float2*)sm;              // [HR][UP] fwd pairs
    float2* s_pw = s_pf + HR * UP;           // [HR][UP] bwd pairs
    __shared__ float s_ja[UP], s_jb[UP];

    const int b    = blockIdx.x;
    const int tid  = threadIdx.x;
    const int lane = tid & 31;
    const int wid  = tid >> 5;

    {   // stage packed tables (coalesced float4, 8 warps)
        const float4* gf = (const float4*)&g_pf[b][0][0];
        const float4* gw = (const float4*)&g_pw[b][0][0];
        float4* sf = (float4*)s_pf;
        float4* sw = (float4*)s_pw;
        const int n4 = HR * UP / 2;          // 5200 float4 per half
        for (int k = tid; k < n4; k += 256) { sf[k] = gf[k]; sw[k] = gw[k]; }
    }
    if (tid < UP) { s_ja[tid] = NEG; s_jb[tid] = 0.0f; }

    const int Tb  = __ldg(Tarr + b);
    const int Ub  = __ldg(Uarr + b);
    const int ts  = (Tb + 1) >> 1;           // fwd rows [0,ts)
    const int nbk = Tb - ts;                 // bwd rows [ts,Tb)
    __syncthreads();

    const int src = (lane + 31) & 31;        // rotate-up source lane

    if (wid == 0) {
        // ---------------- forward: alpha over rows [0, ts) ----------------
        const int R = ts;
        const int nsteps = R + Ub;
        int uu[4], uc[4];
        float jb4[4];
        #pragma unroll
        for (int j = 0; j < 4; ++j) {
            uu[j] = lane + 32 * j;
            uc[j] = min(uu[j], UP - 1);
            jb4[j] = __ldg(&g_jblk[b][uc[j]]);
        }
        float m[4] = {(lane == 0) ? 0.0f : NEG, NEG, NEG, NEG};
        float f[4] = {1.f, 1.f, 1.f, 1.f};

        for (int s0 = 1; s0 < nsteps; s0 += 8) {
            #pragma unroll
            for (int ds = 0; ds < 8; ++ds) {
                const int s = s0 + ds;
                float rm[4], rf[4];
                #pragma unroll
                for (int j = 0; j < 4; ++j) {
                    rm[j] = __shfl_sync(FULL, m[j], src);
                    rf[j] = __shfl_sync(FULL, f[j], src);
                }
                #pragma unroll
                for (int j = 0; j < 4; ++j) {
                    const int t = s - uu[j];
                    const unsigned tc = min((unsigned)t, (unsigned)(R - 1));
                    const float2 pv = s_pf[tc * UP + uc[j]];
                    const float hinm = lane ? rm[j] : (j ? rm[j - 1] : NEG);
                    const float hinf = lane ? rf[j] : (j ? rf[j - 1] : 1.0f);
                    const float verm = m[j] + pv.x;
                    const float horm = hinm + pv.y;
                    const float d  = verm - horm;
                    const float M  = fmaxf(verm, horm);
                    const float e  = ex2(fminf(d, fneg(d)));   // 2^(-|d|)
                    const float fb = (d >= 0.f) ? f[j] : hinf;
                    const float fs = (d >= 0.f) ? hinf : f[j];
                    const float fp = fmaf(fs, e, fb);
                    const bool act = ((unsigned)t < (unsigned)R);
                    m[j] = act ? M  : m[j];
                    f[j] = act ? fp : f[j];
                }
            }
            // exact exponent folding: h = m + lg2(f) unchanged bit-for-bit
            #pragma unroll
            for (int j = 0; j < 4; ++j) {
                const int bi = __float_as_int(f[j]);
                const int ex = (bi >> 23) - 127;
                m[j] += (float)ex;
                f[j] = __int_as_float(bi - (ex << 23));
            }
        }
        // junction row ts-1: ja[u] = alpha[ts-1,u] + blk[ts-1,u]
        #pragma unroll
        for (int j = 0; j < 4; ++j)
            if (uu[j] <= Ub) s_ja[uu[j]] = m[j] + lg2(f[j]) + jb4[j];
    } else if (wid == 1) {
        // ------------- backward: beta rows [ts,Tb), mirrored coords -------
        const int R = nbk;
        const int nsteps = R + Ub;
        const float seedB = s_pw[(R - 1) * UP + Ub].x;     // blk[Tb-1][Ub]
        int vv[4], ucb[4];
        #pragma unroll
        for (int j = 0; j < 4; ++j) {
            vv[j]  = lane + 32 * j;
            ucb[j] = min(max(Ub - vv[j], 0), UP - 1);
        }
        float m[4] = {(lane == 0) ? seedB : NEG, NEG, NEG, NEG};
        float f[4] = {1.f, 1.f, 1.f, 1.f};

        for (int s0 = 1; s0 < nsteps; s0 += 8) {
            #pragma unroll
            for (int ds = 0; ds < 8; ++ds) {
                const int s = s0 + ds;
                float rm[4], rf[4];
                #pragma unroll
                for (int j = 0; j < 4; ++j) {
                    rm[j] = __shfl_sync(FULL, m[j], src);
                    rf[j] = __shfl_sync(FULL, f[j], src);
                }
                #pragma unroll
                for (int j = 0; j < 4; ++j) {
                    const int tp = s - vv[j];
                    const unsigned tpc = min((unsigned)tp, (unsigned)(R - 1));
                    const unsigned rb  = (unsigned)(R - 1) - tpc;
                    const float2 pv = s_pw[rb * UP + ucb[j]];
                    const float hinm = lane ? rm[j] : (j ? rm[j - 1] : NEG);
                    const float hinf = lane ? rf[j] : (j ? rf[j - 1] : 1.0f);
                    const float verm = m[j] + pv.x;        // beta[t+1,u] + blk[t,u]
                    const float horm = hinm + pv.y;        // beta[t,u+1] + emit[t,u]
                    const float d  = verm - horm;
                    const float M  = fmaxf(verm, horm);
                    const float e  = ex2(fminf(d, fneg(d)));
                    const float fb = (d >= 0.f) ? f[j] : hinf;
                    const float fs = (d >= 0.f) ? hinf : f[j];
                    const float fp = fmaf(fs, e, fb);
                    const bool act = ((unsigned)tp < (unsigned)R);
                    m[j] = act ? M  : m[j];
                    f[j] = act ? fp : f[j];
                }
            }
            #pragma unroll
            for (int j = 0; j < 4; ++j) {
                const int bi = __float_as_int(f[j]);
                const int ex = (bi >> 23) - 127;
                m[j] += (float)ex;
                f[j] = __int_as_float(bi - (ex << 23));
            }
        }
        // junction row ts: jb[u] = beta[ts, u]
        #pragma unroll
        for (int j = 0; j < 4; ++j) {
            const int u = Ub - vv[j];
            if (u >= 0) s_jb[u] = m[j] + lg2(f[j]);
        }
    }
    __syncthreads();

    // log_p = LN2 * LSE2_u(ja[u] + jb[u])   (warp 0)
    if (tid < 32) {
        float x0 = (tid      < UP) ? s_ja[tid]      + s_jb[tid]      : NEG;
        float x1 = (tid + 32 < UP) ? s_ja[tid + 32] + s_jb[tid + 32] : NEG;
        float x2 = (tid + 64 < UP) ? s_ja[tid + 64] + s_jb[tid + 64] : NEG;
        float x3 = (tid + 96 < UP) ? s_ja[tid + 96] + s_jb[tid + 96] : NEG;
        float mm = fmaxf(fmaxf(x0, x1), fmaxf(x2, x3));
        #pragma unroll
        for (int o = 16; o > 0; o >>= 1)
            mm = fmaxf(mm, __shfl_xor_sync(FULL, mm, o));
        float sum2 = ex2(x0 - mm) + ex2(x1 - mm) + ex2(x2 - mm) + ex2(x3 - mm);
        #pragma unroll
        for (int o = 16; o > 0; o >>= 1)
            sum2 += __shfl_xor_sync(FULL, sum2, o);
        if (tid == 0) g_logp[b] = (mm + lg2(sum2)) * LN2;
    }
    __syncthreads();

    // fixed-order mean reduction in the last-arriving CTA (deterministic)
    if (tid == 0) {
        __threadfence();
        int old = atomicAdd(&g_cnt, 1);
        if (old == BQ - 1) {
            __threadfence();
            float ssum = 0.0f;
            #pragma unroll
            for (int i = 0; i < BQ; ++i) ssum += g_logp[i];
            out[0] = -ssum / (float)BQ;
            g_cnt = 0;                       // reset for next graph replay
        }
    }
}

extern "C" void kernel_launch(void* const* d_in, const int* in_sizes, int n_in,
                              void* d_out, int out_size)
{
    const float* lp     = (const float*)d_in[0];
    const int*   labels = (const int*)  d_in[1];
    const int*   Tarr   = (const int*)  d_in[2];
    const int*   Uarr   = (const int*)  d_in[3];
    float* out = (float*)d_out;

    const int smem_bytes = 2 * HR * UP * (int)sizeof(float2);  // 166,400
    cudaFuncSetAttribute(tl_lattice_kernel,
                         cudaFuncAttributeMaxDynamicSharedMemorySize,
                         smem_bytes);

    const int total  = BQ * TM * UM;
    const int blocks = (total + 256 * 4 - 1) / (256 * 4);      // 316
    tl_gather_kernel<<<blocks, 256>>>(lp, labels, Tarr);
    tl_lattice_kernel<<<BQ, 256, smem_bytes>>>(Tarr, Uarr, out);
}

// round 15
// speedup vs baseline: 1.2440x; 1.1530x over previous
#include <cuda_runtime.h>

// RNN-T transducer loss. B=16, T=200, U=101, A=512, blank=0.
// LOG2-domain DIAGONAL-split lattice, lazy (m,f) representation
// (h = m + lg2(f)), barrier-free shfl schedule, no freeze selects.
//   identity: log_p = LSE_{t+u=D} alpha[t,u] + beta[t,u],  D=(Tb+Ub)/2
//   warp0: alpha diagonals 1..D   (producer-side pre-adds)
//   warp1: beta  diagonals back to D (consumer-side adds, mirrored coords)
// Single packed table P[t][u] = (blk[t][u], emit[t][u]) in log2 domain.

#define BQ 16
#define TM 200
#define UM 101
#define AA 512
#define UP 104
#define NEG (-1.0e30f)
#define LOG2E 1.4426950408889634f
#define LN2   0.6931471805599453f
#define FULL  0xffffffffu

__device__ __align__(16) float2 g_p[BQ][TM][UP];   // (blk, emit), log2 domain
__device__ float g_logp[BQ];
__device__ int   g_cnt = 0;

__device__ __forceinline__ float ex2(float x) { float y; asm("ex2.approx.f32 %0, %1;" : "=f"(y) : "f"(x)); return y; }
__device__ __forceinline__ float lg2(float x) { float y; asm("lg2.approx.f32 %0, %1;" : "=f"(y) : "f"(x)); return y; }

__global__ void tl_gather_kernel(const float* __restrict__ lp,
                                 const int*   __restrict__ labels)
{
    const int total  = BQ * TM * UM;
    const int stride = gridDim.x * blockDim.x;
    int i0 = blockIdx.x * blockDim.x + threadIdx.x;
    #pragma unroll
    for (int kk = 0; kk < 4; ++kk) {
        int i = i0 + kk * stride;
        if (i < total) {
            int u  = i % UM;
            int bt = i / UM;
            int t  = bt % TM;
            int b  = bt / TM;
            int lab = (u < UM - 1) ? __ldg(labels + b * (UM - 1) + u) : 0;
            size_t base = (size_t)i * AA;
            float bv = __ldg(lp + base) * LOG2E;
            float ev = lab ? __ldg(lp + base + lab) * LOG2E : bv;
            g_p[b][t][u] = make_float2(bv, ev);
        }
    }
}

// fwd step: vm/om are pre-added (value+blk, value+emit); hor arrives pre-added.
__device__ __forceinline__ void fwd_step(int s, int lane, int src,
    const int* uu, const int* uc, const float2* s_p, unsigned Tbm1,
    float* M, float* f, float* vm, float* om)
{
    float hm[4], hf[4];
    #pragma unroll
    for (int j = 0; j < 4; ++j) {
        hm[j] = __shfl_sync(FULL, om[j], src);
        hf[j] = __shfl_sync(FULL, f[j],  src);
    }
    #pragma unroll
    for (int j = 0; j < 4; ++j) {
        const int t = s - uu[j];
        const unsigned tc = min((unsigned)t, Tbm1);
        const float2 pv = s_p[tc * UP + uc[j]];
        const float hinm = lane ? hm[j] : (j ? hm[j - 1] : NEG);
        const float hinf = lane ? hf[j] : (j ? hf[j - 1] : 1.0f);
        const float d  = vm[j] - hinm;
        const float Mx = fmaxf(vm[j], hinm);
        const float e  = ex2(0.0f - fabsf(d));
        const float fb = (d >= 0.0f) ? f[j] : hinf;
        const float fs = (d >= 0.0f) ? hinf : f[j];
        f[j]  = fmaf(fs, e, fb);
        M[j]  = Mx;
        vm[j] = Mx + pv.x;      // pre-add blk[t][u]  -> my ver at (t+1,u)
        om[j] = Mx + pv.y;      // pre-add emit[t][u] -> neighbor hor at (t+1,u+1)
    }
}

// bwd step: consumer-side adds; mirrored coords tp = Tb-1-t, v = Ub-u.
__device__ __forceinline__ void bwd_step(int sp, int lane, int src,
    const int* vv, const int* ucb, const float2* s_p, unsigned Tbm1,
    float* M, float* f)
{
    float hm[4], hf[4];
    #pragma unroll
    for (int j = 0; j < 4; ++j) {
        hm[j] = __shfl_sync(FULL, M[j], src);
        hf[j] = __shfl_sync(FULL, f[j], src);
    }
    #pragma unroll
    for (int j = 0; j < 4; ++j) {
        const int tp = sp - vv[j];
        const unsigned tpc = min((unsigned)tp, Tbm1);
        const unsigned row = Tbm1 - tpc;
        const float2 pv = s_p[row * UP + ucb[j]];
        const float hinm = lane ? hm[j] : (j ? hm[j - 1] : NEG);
        const float hinf = lane ? hf[j] : (j ? hf[j - 1] : 1.0f);
        const float verm = M[j] + pv.x;       // beta[t+1,u] + blk[t,u]
        const float horm = hinm + pv.y;       // beta[t,u+1] + emit[t,u]
        const float d  = verm - horm;
        const float Mx = fmaxf(verm, horm);
        const float e  = ex2(0.0f - fabsf(d));
        const float fb = (d >= 0.0f) ? f[j] : hinf;
        const float fs = (d >= 0.0f) ? hinf : f[j];
        f[j] = fmaf(fs, e, fb);
        M[j] = Mx;
    }
}

__global__ __launch_bounds__(256, 1)
void tl_lattice_kernel(const int* __restrict__ Tarr,
                       const int* __restrict__ Uarr,
                       float* __restrict__ out)
{
    extern __shared__ float2 s_p[];          // [TM][UP] packed pairs
    __shared__ float s_ja[UP], s_jb[UP];

    const int b    = blockIdx.x;
    const int tid  = threadIdx.x;
    const int lane = tid & 31;
    const int wid  = tid >> 5;

    {   // stage table (coalesced float4, 8 warps): 166,400 bytes
        const float4* gp = (const float4*)&g_p[b][0][0];
        float4* sp4 = (float4*)s_p;
        const int n4 = TM * UP * 8 / 16;     // 10400
        for (int k = tid; k < n4; k += 256) sp4[k] = gp[k];
    }
    if (tid < UP) { s_ja[tid] = NEG; s_jb[tid] = NEG; }

    const int Tb  = __ldg(Tarr + b);
    const int Ub  = __ldg(Uarr + b);
    const int D   = (Tb + Ub) >> 1;          // junction diagonal
    const int spD = Tb - 1 + Ub - D;         // bwd step count
    const unsigned Tbm1 = (unsigned)(Tb - 1);
    __syncthreads();

    const int src = (lane + 31) & 31;        // rotate-up source lane

    if (wid == 0) {
        // ---------------- forward alpha to diagonal D ----------------
        int uu[4], uc[4];
        #pragma unroll
        for (int j = 0; j < 4; ++j) { uu[j] = lane + 32 * j; uc[j] = min(uu[j], UP - 1); }
        float M[4], f[4], vm[4], om[4];
        const float2 p00 = s_p[0];
        #pragma unroll
        for (int j = 0; j < 4; ++j) { M[j] = NEG; f[j] = 1.0f; vm[j] = NEG; om[j] = NEG; }
        if (lane == 0) { M[0] = 0.0f; vm[0] = p00.x; om[0] = p00.y; }   // alpha[0,0]=0

        int s = 1;
        const int nf = D >> 3;
        for (int b8 = 0; b8 < nf; ++b8) {
            #pragma unroll
            for (int ds = 0; ds < 8; ++ds) { fwd_step(s, lane, src, uu, uc, s_p, Tbm1, M, f, vm, om); ++s; }
            #pragma unroll
            for (int j = 0; j < 4; ++j) {    // exact exponent folding
                const int bi = __float_as_int(f[j]);
                const int ex = (bi >> 23) - 127;
                const float fe = (float)ex;
                f[j] = __int_as_float(bi - (ex << 23));
                M[j] += fe; vm[j] += fe; om[j] += fe;
            }
        }
        for (; s <= D; ++s) fwd_step(s, lane, src, uu, uc, s_p, Tbm1, M, f, vm, om);

        // junction: alpha[D-u, u]
        #pragma unroll
        for (int j = 0; j < 4; ++j) {
            const int tF = D - uu[j];
            if (tF >= 0 && tF < Tb) s_ja[uu[j]] = M[j] + lg2(f[j]);
        }
    } else if (wid == 1) {
        // ---------------- backward beta to diagonal D ----------------
        int vv[4], ucb[4];
        #pragma unroll
        for (int j = 0; j < 4; ++j) {
            vv[j]  = lane + 32 * j;
            ucb[j] = min(max(Ub - vv[j], 0), UP - 1);
        }
        float M[4], f[4];
        const float2 pTU = s_p[(Tb - 1) * UP + Ub];
        #pragma unroll
        for (int j = 0; j < 4; ++j) { M[j] = NEG; f[j] = 1.0f; }
        if (lane == 0) M[0] = pTU.x;         // beta[Tb-1,Ub] = blk[Tb-1,Ub]

        int sp = 1;
        const int nf = spD >> 3;
        for (int b8 = 0; b8 < nf; ++b8) {
            #pragma unroll
            for (int ds = 0; ds < 8; ++ds) { bwd_step(sp, lane, src, vv, ucb, s_p, Tbm1, M, f); ++sp; }
            #pragma unroll
            for (int j = 0; j < 4; ++j) {
                const int bi = __float_as_int(f[j]);
                const int ex = (bi >> 23) - 127;
                f[j] = __int_as_float(bi - (ex << 23));
                M[j] += (float)ex;
            }
        }
        for (; sp <= spD; ++sp) bwd_step(sp, lane, src, vv, ucb, s_p, Tbm1, M, f);

        // junction: beta[D-u, u] with u = Ub-v
        #pragma unroll
        for (int j = 0; j < 4; ++j) {
            const int tF = spD - vv[j];
            const int u2 = Ub - vv[j];
            if (tF >= 0 && tF < Tb && u2 >= 0) s_jb[u2] = M[j] + lg2(f[j]);
        }
    }
    __syncthreads();

    // log_p = LN2 * LSE2_u(ja[u] + jb[u])   (warp 0)
    if (tid < 32) {
        float x0 = (tid      < UP) ? s_ja[tid]      + s_jb[tid]      : NEG;
        float x1 = (tid + 32 < UP) ? s_ja[tid + 32] + s_jb[tid + 32] : NEG;
        float x2 = (tid + 64 < UP) ? s_ja[tid + 64] + s_jb[tid + 64] : NEG;
        float x3 = (tid + 96 < UP) ? s_ja[tid + 96] + s_jb[tid + 96] : NEG;
        float mm = fmaxf(fmaxf(x0, x1), fmaxf(x2, x3));
        #pragma unroll
        for (int o = 16; o > 0; o >>= 1)
            mm = fmaxf(mm, __shfl_xor_sync(FULL, mm, o));
        float sum2 = ex2(x0 - mm) + ex2(x1 - mm) + ex2(x2 - mm) + ex2(x3 - mm);
        #pragma unroll
        for (int o = 16; o > 0; o >>= 1)
            sum2 += __shfl_xor_sync(FULL, sum2, o);
        if (tid == 0) g_logp[b] = (mm + lg2(sum2)) * LN2;
    }
    __syncthreads();

    // fixed-order mean reduction in the last-arriving CTA (deterministic)
    if (tid == 0) {
        __threadfence();
        int old = atomicAdd(&g_cnt, 1);
        if (old == BQ - 1) {
            __threadfence();
            float ssum = 0.0f;
            #pragma unroll
            for (int i = 0; i < BQ; ++i) ssum += g_logp[i];
            out[0] = -ssum / (float)BQ;
            g_cnt = 0;                       // reset for next graph replay
        }
    }
}

extern "C" void kernel_launch(void* const* d_in, const int* in_sizes, int n_in,
                              void* d_out, int out_size)
{
    const float* lp     = (const float*)d_in[0];
    const int*   labels = (const int*)  d_in[1];
    const int*   Tarr   = (const int*)  d_in[2];
    const int*   Uarr   = (const int*)  d_in[3];
    float* out = (float*)d_out;

    const int smem_bytes = TM * UP * (int)sizeof(float2);      // 166,400
    cudaFuncSetAttribute(tl_lattice_kernel,
                         cudaFuncAttributeMaxDynamicSharedMemorySize,
                         smem_bytes);

    const int total  = BQ * TM * UM;
    const int blocks = (total + 256 * 4 - 1) / (256 * 4);      // 316
    tl_gather_kernel<<<blocks, 256>>>(lp, labels);
    tl_lattice_kernel<<<BQ, 256, smem_bytes>>>(Tarr, Uarr, out);
}